// round 8
// baseline (speedup 1.0000x reference)
#include <cuda_runtime.h>
#include <cuda_bf16.h>
#include <cstdint>

// Content-addressed select: out = cached_outputs[idx] where idx = first
// fingerprint row equal to x[0..3], else 0. Pure HBM stream copy:
// 256 MiB read + 256 MiB write. DRAM-roofline bound.
//
// R8: single change vs R6 (82.7us, DRAM 79.2%, two-phase 8-burst): WARP-
// CONTIGUOUS addressing. Each warp owns a contiguous 4 KiB region; its
// 8-load burst covers one DRAM page run (max row-buffer hits), instead of
// 8 lines 32 MB apart. Two-phase body, __ldcs/__stcs, 8192 blk x 256 thr.

static constexpr long long SLAB_ELEMS = 16384LL * 4096LL;   // 67,108,864 floats
static constexpr long long N4         = SLAB_ELEMS / 4;     // 16,777,216 float4
static constexpr int       N_CASES    = 6;

static constexpr int THREADS = 256;
static constexpr int ITERS   = 8;                             // float4 per thread
static constexpr int BLOCKS  = (int)(N4 / ((long long)ITERS * THREADS)); // 8192
static_assert((long long)BLOCKS * ITERS * THREADS == N4, "exact cover");

static constexpr int WARP_ELEMS = 32 * ITERS;                 // 256 float4 = 4 KiB

__device__ __forceinline__ int select_idx(const float* __restrict__ x,
                                          const float* __restrict__ fp) {
    // Probe = first 4 floats of x. Broadcast loads — L2 hit for all threads.
    const float p0 = __ldg(&x[0]);
    const float p1 = __ldg(&x[1]);
    const float p2 = __ldg(&x[2]);
    const float p3 = __ldg(&x[3]);
    int idx = 0;
    // Reverse iteration: lowest matching index wins (== argmax of first True);
    // no match leaves idx = 0.
    #pragma unroll
    for (int i = N_CASES - 1; i >= 0; --i) {
        const float f0 = __ldg(&fp[i * 4 + 0]);
        const float f1 = __ldg(&fp[i * 4 + 1]);
        const float f2 = __ldg(&fp[i * 4 + 2]);
        const float f3 = __ldg(&fp[i * 4 + 3]);
        if (f0 == p0 && f1 == p1 && f2 == p2 && f3 == p3) idx = i;
    }
    return idx;
}

__global__ __launch_bounds__(THREADS)
void cache_select_copy_kernel(const float* __restrict__ x,
                              const float* __restrict__ fingerprints,
                              const float4* __restrict__ cached,
                              float4* __restrict__ out) {
    const int idx = select_idx(x, fingerprints);
    const float4* __restrict__ src = cached + (long long)idx * N4;

    // Warp-contiguous: warp w (global) owns float4 range
    // [w*256, (w+1)*256): a contiguous 4 KiB region. Iteration it covers
    // lanes at base + it*32 -> the warp's 8-iteration burst walks one
    // contiguous 4 KiB DRAM page run.
    const int       lane  = threadIdx.x & 31;
    const long long gwarp = ((long long)blockIdx.x * THREADS + threadIdx.x) >> 5;
    const long long base  = gwarp * WARP_ELEMS + lane;

    // Phase 1: 8 independent LDG.128 back-to-back — one contiguous read burst.
    float4 v[ITERS];
    #pragma unroll
    for (int it = 0; it < ITERS; ++it) {
        v[it] = __ldcs(&src[base + it * 32]);
    }

    // Phase 2: 8 STG.128 back-to-back — one contiguous write burst.
    #pragma unroll
    for (int it = 0; it < ITERS; ++it) {
        __stcs(&out[base + it * 32], v[it]);
    }
}

extern "C" void kernel_launch(void* const* d_in, const int* in_sizes, int n_in,
                              void* d_out, int out_size) {
    const float*  x      = (const float*)d_in[0];
    const float*  fps    = (const float*)d_in[1];
    const float4* cached = (const float4*)d_in[2];
    float4*       out    = (float4*)d_out;

    cache_select_copy_kernel<<<BLOCKS, THREADS>>>(x, fps, cached, out);
}